// round 4
// baseline (speedup 1.0000x reference)
#include <cuda_runtime.h>

#define NT     256
#define NBLK   256
#define PG     4
#define DD     64
#define HH     2048
#define CCH    256
#define NCHK   8
#define MAXPTS 512

__device__ float g_a[64 * HH];
__device__ float g_asp[MAXPTS * HH];
__device__ float g_wpart[NCHK * MAXPTS * DD];
__device__ float g_cpart[NCHK * MAXPTS * DD];
__device__ unsigned g_bar_cnt;
__device__ unsigned g_bar_gen;

__device__ __forceinline__ void grid_barrier()
{
    __threadfence();
    __syncthreads();
    if (threadIdx.x == 0) {
        volatile unsigned* genp = &g_bar_gen;
        unsigned gen = *genp;
        unsigned t = atomicAdd(&g_bar_cnt, 1u);
        if (t == NBLK - 1) {
            g_bar_cnt = 0;
            __threadfence();
            atomicAdd(&g_bar_gen, 1u);
        } else {
            while (*genp == gen) __nanosleep(32);
        }
    }
    __syncthreads();
}

__device__ __forceinline__ void load_chunk_async(float* buf, const float* __restrict__ W1,
                                                 int j0, int tid)
{
    #pragma unroll
    for (int s = 0; s < 16; ++s) {
        int g = s * NT + tid;            // 4096 16B segments
        int d = g >> 6;
        int k = g & 63;
        const float* src = W1 + d * HH + j0 + k * 4;
        unsigned dst = (unsigned)__cvta_generic_to_shared(buf + d * CCH + k * 4);
        asm volatile("cp.async.cg.shared.global [%0], [%1], 16;" :: "r"(dst), "l"(src));
    }
    asm volatile("cp.async.commit_group;");
}

__global__ __launch_bounds__(NT, 2) void fused_geo(
    const float* __restrict__ x0, const float* __restrict__ xT,
    const float* __restrict__ W1, const float* __restrict__ b1,
    const float* __restrict__ W2, float* __restrict__ out,
    int B, int O, int n_steps, int nInterior)
{
    extern __shared__ float sm[];
    float* W1s  = sm;                    // 64*256 = 16384 floats
    float* xp   = W1s + DD * CCH;        // [d][p] : 256  (also wp in phase B)
    float* as_t = xp + DD * PG;          // [j][p] : 1024 (also csh in phase C)
    float* vsh  = as_t + CCH * PG;       // 64
    float* red  = vsh + DD;              // 8

    int tid = threadIdx.x, lane = tid & 31, warp = tid >> 5;
    int bid = blockIdx.x;
    int c = bid & 7;                     // W1 chunk (and h-slice in phase 0)
    int slice = bid >> 3;                // 0..31 (batch in phase 0; group-slice later)
    float invn1 = 1.0f / (float)(n_steps - 1);

    // kick off this block's W1 chunk load; it stays resident all kernel
    load_chunk_async(W1s, W1, c * CCH, tid);

    // ================= phase 0: a = W2 . normalize(xT-x0) ; boundaries ======
    for (int b = slice; b < B || b == slice; b += 32) {
        int bc = (b < B) ? b : (B - 1);
        if (tid < DD) vsh[tid] = xT[bc * DD + tid] - x0[bc * DD + tid];
        __syncthreads();
        if (warp == 0) {
            float s = vsh[lane] * vsh[lane] + vsh[lane + 32] * vsh[lane + 32];
            #pragma unroll
            for (int o = 16; o; o >>= 1) s += __shfl_xor_sync(0xffffffffu, s, o);
            if (lane == 0) red[0] = 1.0f / sqrtf(s);
        }
        __syncthreads();
        float inv = red[0];
        if (tid < DD) vsh[tid] *= inv;
        __syncthreads();

        int h = c * CCH + tid;
        const float4* w2r = (const float4*)(W2 + (size_t)h * O);
        const float4* v4 = (const float4*)vsh;
        float acc = 0.f;
        #pragma unroll
        for (int k = 0; k < 16; ++k) {
            float4 w = w2r[k], vv = v4[k];
            acc += w.x * vv.x + w.y * vv.y + w.z * vv.z + w.w * vv.w;
        }
        g_a[bc * HH + h] = acc;

        if (c == 0 && tid < DD) {
            out[bc * DD + tid] = x0[bc * DD + tid];
            out[((n_steps - 1) * B + bc) * DD + tid] = xT[bc * DD + tid];
        }
        __syncthreads();
        if (b >= B) break;
    }

    asm volatile("cp.async.wait_group 0;");
    grid_barrier();

    // ================= phase A: h -> as/asp ; partial w =====================
    #pragma unroll
    for (int k = 0; k < 2; ++k) {
        int g = slice * 2 + k;
        int gpbase = g * PG;
        {
            int p = tid >> 6, m = tid & (DD - 1);
            int gp = gpbase + p; if (gp >= nInterior) gp = nInterior - 1;
            int s = gp / B + 1;
            int b = gp % B;
            float t = (float)s * invn1;
            float a0 = x0[b * DD + m];
            xp[m * PG + p] = a0 + t * (xT[b * DD + m] - a0);
        }
        __syncthreads();

        // column pass: h_j for 4 points
        int j = c * CCH + tid;
        float bj = b1[j];
        float h0 = bj, h1 = bj, h2 = bj, h3 = bj;
        const float4* xpv = (const float4*)xp;
        #pragma unroll 8
        for (int d = 0; d < DD; ++d) {
            float wv = W1s[d * CCH + tid];
            float4 xv = xpv[d];
            h0 += xv.x * wv; h1 += xv.y * wv; h2 += xv.z * wv; h3 += xv.w * wv;
        }
        {
            float hv[PG] = {h0, h1, h2, h3};
            float asv[PG];
            #pragma unroll
            for (int p = 0; p < PG; ++p) {
                int gp = gpbase + p; if (gp >= nInterior) gp = nInterior - 1;
                int b = gp % B;
                float a = __ldcg(&g_a[b * HH + j]);
                float t = tanhf(hv[p]);
                float sf = 1.0f - t * t;
                asv[p] = a * sf;
                g_asp[(size_t)gp * HH + j] = a * (-2.0f * t * sf);
            }
            ((float4*)as_t)[tid] = make_float4(asv[0], asv[1], asv[2], asv[3]);
        }
        __syncthreads();

        // row pass: warp handles rows warp*8..+7
        float acc[8][PG];
        #pragma unroll
        for (int r = 0; r < 8; ++r)
            #pragma unroll
            for (int p = 0; p < PG; ++p) acc[r][p] = 0.f;
        const float4* as4 = (const float4*)as_t;
        #pragma unroll
        for (int jj = 0; jj < 8; ++jj) {
            int j2 = jj * 32 + lane;
            float4 av = as4[j2];
            #pragma unroll
            for (int r = 0; r < 8; ++r) {
                float wv = W1s[(warp * 8 + r) * CCH + j2];
                acc[r][0] += wv * av.x; acc[r][1] += wv * av.y;
                acc[r][2] += wv * av.z; acc[r][3] += wv * av.w;
            }
        }
        #pragma unroll
        for (int r = 0; r < 8; ++r)
            #pragma unroll
            for (int p = 0; p < PG; ++p) {
                float v = acc[r][p];
                #pragma unroll
                for (int o = 16; o; o >>= 1) v += __shfl_xor_sync(0xffffffffu, v, o);
                if (lane == 0) {
                    int gp = gpbase + p; if (gp >= nInterior) gp = nInterior - 1;
                    g_wpart[(c * MAXPTS + gp) * DD + warp * 8 + r] = v;
                }
            }
        __syncthreads();
    }

    grid_barrier();

    // ================= phase B: q -> m = asp*q ; partial corr ===============
    #pragma unroll
    for (int k = 0; k < 2; ++k) {
        int g = slice * 2 + k;
        int gpbase = g * PG;
        {
            int d = tid >> 2, p = tid & 3;
            int gp = gpbase + p; if (gp >= nInterior) gp = nInterior - 1;
            float s = 0.f;
            #pragma unroll
            for (int cc = 0; cc < NCHK; ++cc)
                s += __ldcg(&g_wpart[(cc * MAXPTS + gp) * DD + d]);
            xp[tid] = s;                 // [d][p] layout
        }
        __syncthreads();

        int j = c * CCH + tid;
        float q0 = 0.f, q1 = 0.f, q2 = 0.f, q3 = 0.f;
        const float4* wpv = (const float4*)xp;
        #pragma unroll 8
        for (int d = 0; d < DD; ++d) {
            float wv = W1s[d * CCH + tid];
            float4 wc = wpv[d];
            q0 += wc.x * wv; q1 += wc.y * wv; q2 += wc.z * wv; q3 += wc.w * wv;
        }
        {
            float qv[PG] = {q0, q1, q2, q3};
            float mv[PG];
            #pragma unroll
            for (int p = 0; p < PG; ++p) {
                int gp = gpbase + p; if (gp >= nInterior) gp = nInterior - 1;
                mv[p] = __ldcg(&g_asp[(size_t)gp * HH + j]) * qv[p];
            }
            ((float4*)as_t)[tid] = make_float4(mv[0], mv[1], mv[2], mv[3]);
        }
        __syncthreads();

        float acc[8][PG];
        #pragma unroll
        for (int r = 0; r < 8; ++r)
            #pragma unroll
            for (int p = 0; p < PG; ++p) acc[r][p] = 0.f;
        const float4* m4 = (const float4*)as_t;
        #pragma unroll
        for (int jj = 0; jj < 8; ++jj) {
            int j2 = jj * 32 + lane;
            float4 av = m4[j2];
            #pragma unroll
            for (int r = 0; r < 8; ++r) {
                float wv = W1s[(warp * 8 + r) * CCH + j2];
                acc[r][0] += wv * av.x; acc[r][1] += wv * av.y;
                acc[r][2] += wv * av.z; acc[r][3] += wv * av.w;
            }
        }
        #pragma unroll
        for (int r = 0; r < 8; ++r)
            #pragma unroll
            for (int p = 0; p < PG; ++p) {
                float v = acc[r][p];
                #pragma unroll
                for (int o = 16; o; o >>= 1) v += __shfl_xor_sync(0xffffffffu, v, o);
                if (lane == 0) {
                    int gp = gpbase + p; if (gp >= nInterior) gp = nInterior - 1;
                    g_cpart[(c * MAXPTS + gp) * DD + warp * 8 + r] = v;
                }
            }
        __syncthreads();
    }

    grid_barrier();

    // ================= phase C: reduce corr, scale, epilogue ================
    if (bid * PG < nInterior && bid < 64) {
        int g = bid;
        float* csh = as_t;               // PG*64
        float* sc  = red;                // PG
        {
            int d = tid >> 2, p = tid & 3;
            int gp = g * PG + p; if (gp >= nInterior) gp = nInterior - 1;
            float s = 0.f;
            #pragma unroll
            for (int cc = 0; cc < NCHK; ++cc)
                s += __ldcg(&g_cpart[(cc * MAXPTS + gp) * DD + d]);
            csh[p * DD + d] = -s;
        }
        __syncthreads();
        if (warp < PG) {
            int p = warp;
            float c0 = csh[p * DD + lane], c1 = csh[p * DD + 32 + lane];
            float s = c0 * c0 + c1 * c1;
            #pragma unroll
            for (int o = 16; o; o >>= 1) s += __shfl_xor_sync(0xffffffffu, s, o);
            if (lane == 0) sc[p] = fminf(sqrtf(s), 0.1f) * 0.1f;
        }
        __syncthreads();
        {
            int p = tid >> 6, m = tid & (DD - 1);
            int gp = g * PG + p;
            if (gp < nInterior) {
                int s = gp / B + 1;
                int b = gp % B;
                float t = (float)s * invn1;
                float a0 = x0[b * DD + m];
                float xv = a0 + t * (xT[b * DD + m] - a0);
                float tfac = t * (1.0f - t);
                out[(gp + B) * DD + m] = xv + csh[p * DD + m] * tfac * sc[p];
            }
        }
    }
}

extern "C" void kernel_launch(void* const* d_in, const int* in_sizes, int n_in,
                              void* d_out, int out_size)
{
    const float* x0 = (const float*)d_in[0];
    const float* xT = (const float*)d_in[1];
    const float* W1 = (const float*)d_in[2];
    const float* b1 = (const float*)d_in[3];
    const float* W2 = (const float*)d_in[4];
    float* out = (float*)d_out;

    int H = in_sizes[3];               // 2048
    int Dd = in_sizes[2] / H;          // 64
    int B = in_sizes[0] / Dd;          // 32
    int O = in_sizes[5];               // 64
    int n_steps = out_size / (B * Dd); // 10
    int nInterior = (n_steps - 2) * B; // 256

    size_t smem = (size_t)(DD * CCH + DD * PG + CCH * PG + DD + 8) * sizeof(float);
    static int attr_set = 0;
    if (!attr_set) {
        cudaFuncSetAttribute(fused_geo, cudaFuncAttributeMaxDynamicSharedMemorySize, (int)smem);
        attr_set = 1;
    }
    fused_geo<<<NBLK, NT, smem>>>(x0, xT, W1, b1, W2, out, B, O, n_steps, nInterior);
}

// round 5
// speedup vs baseline: 1.3369x; 1.3369x over previous
#include <cuda_runtime.h>

#define NT     256
#define PG     4
#define DD     64
#define HH     2048
#define CCH    256
#define NCHK   8
#define MAXPTS 512
#define MAXGRP 128

__device__ float g_asp[MAXPTS * HH];              // a * s' per point
__device__ float g_wpart[NCHK * MAXPTS * DD];     // partial w
__device__ float g_cpart[NCHK * MAXPTS * DD];     // partial corr (unnegated)
__device__ unsigned g_done[MAXGRP];               // per-group arrival counters

__device__ __forceinline__ void load_chunk_async(float* buf, const float* __restrict__ W1,
                                                 int j0, int tid)
{
    #pragma unroll
    for (int s = 0; s < 16; ++s) {
        int g = s * NT + tid;            // 4096 16B segments
        int d = g >> 6;
        int k = g & 63;
        const float* src = W1 + d * HH + j0 + k * 4;
        unsigned dst = (unsigned)__cvta_generic_to_shared(buf + d * CCH + k * 4);
        asm volatile("cp.async.cg.shared.global [%0], [%1], 16;" :: "r"(dst), "l"(src));
    }
    asm volatile("cp.async.commit_group;");
}

// ------------------------------------------------------------------
// Kernel 1: block (g,c).  Points are BATCH-MAJOR: gp = b*(n-2) + si.
// Computes v_b, a-slice, straight pts, h -> as/asp, partial w.
// ------------------------------------------------------------------
__global__ __launch_bounds__(NT, 3) void k1(
    const float* __restrict__ x0, const float* __restrict__ xT,
    const float* __restrict__ W1, const float* __restrict__ b1,
    const float* __restrict__ W2, float* __restrict__ out,
    int B, int O, int n_steps, int nInterior)
{
    extern __shared__ float sm[];
    float* W1s  = sm;                    // 64*256
    float* a_sh = W1s + DD * CCH;        // PG*CCH
    float* xp   = a_sh + PG * CCH;       // [m][p] : 256
    float* as_t = xp + DD * PG;          // [j][p] : 1024
    float* vsh  = as_t + CCH * PG;       // 64
    float* red  = vsh + DD;              // 8

    int tid = threadIdx.x, lane = tid & 31, warp = tid >> 5;
    int g = blockIdx.x, c = blockIdx.y;
    int j0 = c * CCH;
    int nsPerB = n_steps - 2;
    float invn1 = 1.0f / (float)(n_steps - 1);

    load_chunk_async(W1s, W1, j0, tid);

    int gpc[PG], bb[PG];
    #pragma unroll
    for (int p = 0; p < PG; ++p) {
        int gp = g * PG + p; if (gp >= nInterior) gp = nInterior - 1;
        gpc[p] = gp; bb[p] = gp / nsPerB;
    }

    // straight-line points -> xp[m*PG+p]
    {
        int p = tid >> 6, m = tid & (DD - 1);
        int gp = gpc[p];
        int si = gp % nsPerB;
        int b  = gp / nsPerB;
        float t = (float)(si + 1) * invn1;
        float a0 = x0[b * DD + m];
        xp[m * PG + p] = a0 + t * (xT[b * DD + m] - a0);
    }

    // a-slices per distinct (adjacent-dedup) batch
    int j = j0 + tid;
    #pragma unroll
    for (int p = 0; p < PG; ++p) {
        if (p == 0 || bb[p] != bb[p - 1]) {
            int b = bb[p];
            __syncthreads();                         // protect vsh reuse
            if (tid < DD) vsh[tid] = xT[b * DD + tid] - x0[b * DD + tid];
            __syncthreads();
            if (warp == 0) {
                float s = vsh[lane] * vsh[lane] + vsh[lane + 32] * vsh[lane + 32];
                #pragma unroll
                for (int o = 16; o; o >>= 1) s += __shfl_xor_sync(0xffffffffu, s, o);
                if (lane == 0) red[0] = 1.0f / sqrtf(s);
            }
            __syncthreads();
            float inv = red[0];
            const float4* w2r = (const float4*)(W2 + (size_t)j * O);
            const float4* v4  = (const float4*)vsh;
            float acc = 0.f;
            #pragma unroll
            for (int k = 0; k < 16; ++k) {
                float4 w = w2r[k], vv = v4[k];
                acc += w.x * vv.x + w.y * vv.y + w.z * vv.z + w.w * vv.w;
            }
            a_sh[p * CCH + tid] = acc * inv;

            if (c == 0 && tid < DD) {                // boundary rows (idempotent dups)
                out[b * DD + tid] = x0[b * DD + tid];
                out[((n_steps - 1) * B + b) * DD + tid] = xT[b * DD + tid];
            }
        } else {
            a_sh[p * CCH + tid] = a_sh[(p - 1) * CCH + tid];
        }
    }

    asm volatile("cp.async.wait_group 0;");
    __syncthreads();

    // column pass: h_j for 4 points
    float bj = b1[j];
    float h0 = bj, h1 = bj, h2 = bj, h3 = bj;
    const float4* xpv = (const float4*)xp;
    #pragma unroll 8
    for (int d = 0; d < DD; ++d) {
        float wv = W1s[d * CCH + tid];
        float4 xv = xpv[d];
        h0 += xv.x * wv; h1 += xv.y * wv; h2 += xv.z * wv; h3 += xv.w * wv;
    }
    {
        float hv[PG] = {h0, h1, h2, h3};
        float asv[PG];
        #pragma unroll
        for (int p = 0; p < PG; ++p) {
            float a = a_sh[p * CCH + tid];
            float t = tanhf(hv[p]);
            float sf = 1.0f - t * t;
            asv[p] = a * sf;
            g_asp[(size_t)gpc[p] * HH + j] = a * (-2.0f * t * sf);
        }
        ((float4*)as_t)[tid] = make_float4(asv[0], asv[1], asv[2], asv[3]);
    }
    __syncthreads();

    // row pass: warp handles rows warp*8..+7
    float acc[8][PG];
    #pragma unroll
    for (int r = 0; r < 8; ++r)
        #pragma unroll
        for (int p = 0; p < PG; ++p) acc[r][p] = 0.f;
    const float4* as4 = (const float4*)as_t;
    #pragma unroll
    for (int jj = 0; jj < 8; ++jj) {
        int j2 = jj * 32 + lane;
        float4 av = as4[j2];
        #pragma unroll
        for (int r = 0; r < 8; ++r) {
            float wv = W1s[(warp * 8 + r) * CCH + j2];
            acc[r][0] += wv * av.x; acc[r][1] += wv * av.y;
            acc[r][2] += wv * av.z; acc[r][3] += wv * av.w;
        }
    }
    #pragma unroll
    for (int r = 0; r < 8; ++r)
        #pragma unroll
        for (int p = 0; p < PG; ++p) {
            float v = acc[r][p];
            #pragma unroll
            for (int o = 16; o; o >>= 1) v += __shfl_xor_sync(0xffffffffu, v, o);
            if (lane == 0)
                g_wpart[(c * MAXPTS + gpc[p]) * DD + warp * 8 + r] = v;
        }
}

// ------------------------------------------------------------------
// Kernel 2: reduce w ; q ; m = asp*q ; partial corr ; last block of
// each group does the epilogue (no third launch).
// ------------------------------------------------------------------
__global__ __launch_bounds__(NT, 3) void k2(
    const float* __restrict__ x0, const float* __restrict__ xT,
    const float* __restrict__ W1, float* __restrict__ out,
    int B, int n_steps, int nInterior)
{
    extern __shared__ float sm[];
    float* W1s  = sm;                    // 64*256
    float* wp_t = W1s + DD * CCH;        // [d][p] : 256
    float* as_t = wp_t + DD * PG;        // [j][p] : 1024  (csh in epilogue)
    float* red  = as_t + CCH * PG;       // 8
    __shared__ int is_last;

    int tid = threadIdx.x, lane = tid & 31, warp = tid >> 5;
    int g = blockIdx.x, c = blockIdx.y;
    int j0 = c * CCH;
    int nsPerB = n_steps - 2;
    float invn1 = 1.0f / (float)(n_steps - 1);

    load_chunk_async(W1s, W1, j0, tid);

    int gpc[PG];
    #pragma unroll
    for (int p = 0; p < PG; ++p) {
        int gp = g * PG + p; if (gp >= nInterior) gp = nInterior - 1;
        gpc[p] = gp;
    }

    // reduce w partials: thread (d = tid>>2, p = tid&3)
    {
        int d = tid >> 2, p = tid & 3;
        int gp = gpc[p];
        float s = 0.f;
        #pragma unroll
        for (int cc = 0; cc < NCHK; ++cc)
            s += g_wpart[(cc * MAXPTS + gp) * DD + d];
        wp_t[tid] = s;
    }

    asm volatile("cp.async.wait_group 0;");
    __syncthreads();

    int j = j0 + tid;
    float q0 = 0.f, q1 = 0.f, q2 = 0.f, q3 = 0.f;
    const float4* wpv = (const float4*)wp_t;
    #pragma unroll 8
    for (int d = 0; d < DD; ++d) {
        float wv = W1s[d * CCH + tid];
        float4 wc = wpv[d];
        q0 += wc.x * wv; q1 += wc.y * wv; q2 += wc.z * wv; q3 += wc.w * wv;
    }
    {
        float qv[PG] = {q0, q1, q2, q3};
        float mv[PG];
        #pragma unroll
        for (int p = 0; p < PG; ++p)
            mv[p] = __ldcg(&g_asp[(size_t)gpc[p] * HH + j]) * qv[p];
        ((float4*)as_t)[tid] = make_float4(mv[0], mv[1], mv[2], mv[3]);
    }
    __syncthreads();

    float acc[8][PG];
    #pragma unroll
    for (int r = 0; r < 8; ++r)
        #pragma unroll
        for (int p = 0; p < PG; ++p) acc[r][p] = 0.f;
    const float4* m4 = (const float4*)as_t;
    #pragma unroll
    for (int jj = 0; jj < 8; ++jj) {
        int j2 = jj * 32 + lane;
        float4 av = m4[j2];
        #pragma unroll
        for (int r = 0; r < 8; ++r) {
            float wv = W1s[(warp * 8 + r) * CCH + j2];
            acc[r][0] += wv * av.x; acc[r][1] += wv * av.y;
            acc[r][2] += wv * av.z; acc[r][3] += wv * av.w;
        }
    }
    #pragma unroll
    for (int r = 0; r < 8; ++r)
        #pragma unroll
        for (int p = 0; p < PG; ++p) {
            float v = acc[r][p];
            #pragma unroll
            for (int o = 16; o; o >>= 1) v += __shfl_xor_sync(0xffffffffu, v, o);
            if (lane == 0)
                g_cpart[(c * MAXPTS + gpc[p]) * DD + warp * 8 + r] = v;
        }

    // ---- last-block-done epilogue ----
    __threadfence();
    __syncthreads();
    if (tid == 0) {
        unsigned old = atomicAdd(&g_done[g], 1u);
        is_last = (old == NCHK - 1);
    }
    __syncthreads();
    if (!is_last) return;
    __threadfence();

    float* csh = as_t;                   // PG*DD
    {
        int d = tid >> 2, p = tid & 3;
        int gp = gpc[p];
        float s = 0.f;
        #pragma unroll
        for (int cc = 0; cc < NCHK; ++cc)
            s += __ldcg(&g_cpart[(cc * MAXPTS + gp) * DD + d]);
        csh[p * DD + d] = -s;
    }
    __syncthreads();
    if (warp < PG) {
        int p = warp;
        float c0 = csh[p * DD + lane], c1 = csh[p * DD + 32 + lane];
        float s = c0 * c0 + c1 * c1;
        #pragma unroll
        for (int o = 16; o; o >>= 1) s += __shfl_xor_sync(0xffffffffu, s, o);
        if (lane == 0) red[p] = fminf(sqrtf(s), 0.1f) * 0.1f;
    }
    __syncthreads();
    {
        int p = tid >> 6, m = tid & (DD - 1);
        int gp = g * PG + p;
        if (gp < nInterior) {
            int si = gp % nsPerB;
            int b  = gp / nsPerB;
            float t = (float)(si + 1) * invn1;
            float a0 = x0[b * DD + m];
            float xv = a0 + t * (xT[b * DD + m] - a0);
            float tfac = t * (1.0f - t);
            out[((si + 1) * B + b) * DD + m] = xv + csh[p * DD + m] * tfac * red[p];
        }
    }
    if (tid == 0) g_done[g] = 0;         // reset for next graph replay
}

extern "C" void kernel_launch(void* const* d_in, const int* in_sizes, int n_in,
                              void* d_out, int out_size)
{
    const float* x0 = (const float*)d_in[0];
    const float* xT = (const float*)d_in[1];
    const float* W1 = (const float*)d_in[2];
    const float* b1 = (const float*)d_in[3];
    const float* W2 = (const float*)d_in[4];
    float* out = (float*)d_out;

    int H = in_sizes[3];               // 2048
    int Dd = in_sizes[2] / H;          // 64
    int B = in_sizes[0] / Dd;          // 32
    int O = in_sizes[5];               // 64
    int n_steps = out_size / (B * Dd); // 10
    int nInterior = (n_steps - 2) * B; // 256

    int NG = (nInterior + PG - 1) / PG;    // 64

    size_t smem1 = (size_t)(DD * CCH + PG * CCH + DD * PG + CCH * PG + DD + 8) * sizeof(float);
    size_t smem2 = (size_t)(DD * CCH + DD * PG + CCH * PG + 8) * sizeof(float);
    static int attr_set = 0;
    if (!attr_set) {
        cudaFuncSetAttribute(k1, cudaFuncAttributeMaxDynamicSharedMemorySize, (int)smem1);
        cudaFuncSetAttribute(k2, cudaFuncAttributeMaxDynamicSharedMemorySize, (int)smem2);
        attr_set = 1;
    }
    dim3 grid(NG, NCHK);
    k1<<<grid, NT, smem1>>>(x0, xT, W1, b1, W2, out, B, O, n_steps, nInterior);
    k2<<<grid, NT, smem2>>>(x0, xT, W1, out, B, n_steps, nInterior);
}

// round 6
// speedup vs baseline: 1.7472x; 1.3069x over previous
#include <cuda_runtime.h>

#define NT    256
#define PG    8                  // points per group (= n_steps-2 here)
#define DD    64
#define HH    2048
#define CCH   256
#define NCHK  8
#define MAXB  64

__device__ float g_wpart[MAXB * NCHK * DD * PG];
__device__ float g_cpart[MAXB * NCHK * DD * PG];
__device__ unsigned g_cntA[MAXB];
__device__ unsigned g_cntB[MAXB];

__device__ __forceinline__ void load_chunk_async(float* buf, const float* __restrict__ W1,
                                                 int j0, int tid)
{
    #pragma unroll
    for (int s = 0; s < 16; ++s) {
        int g = s * NT + tid;            // 4096 16B segments
        int d = g >> 6;
        int k = g & 63;
        const float* src = W1 + d * HH + j0 + k * 4;
        unsigned dst = (unsigned)__cvta_generic_to_shared(buf + d * CCH + k * 4);
        asm volatile("cp.async.cg.shared.global [%0], [%1], 16;" :: "r"(dst), "l"(src));
    }
    asm volatile("cp.async.commit_group;");
}

__global__ __launch_bounds__(NT, 2) void geo_one(
    const float* __restrict__ x0, const float* __restrict__ xT,
    const float* __restrict__ W1, const float* __restrict__ b1,
    const float* __restrict__ W2, float* __restrict__ out,
    int B, int O, int n_steps, int nInterior)
{
    extern __shared__ float sm[];
    float* W1s   = sm;                   // 16384
    float* a_sh  = W1s + DD * CCH;       // 256
    float* asp_t = a_sh + CCH;           // CCH*PG = 2048
    float* as_t  = asp_t + CCH * PG;     // 2048
    float* xp    = as_t + CCH * PG;      // DD*PG = 512
    float* wp    = xp + DD * PG;         // 512
    float* csh   = wp + DD * PG;         // 512
    float* vsh   = csh + PG * DD;        // 64
    float* red   = vsh + DD;             // 16
    __shared__ int slast;

    int tid = threadIdx.x, lane = tid & 31, warp = tid >> 5;
    int g = blockIdx.x;                  // batch index
    int c = blockIdx.y;                  // W1 chunk
    int j0 = c * CCH;
    int nsPerB = n_steps - 2;            // <= PG
    float invn1 = 1.0f / (float)(n_steps - 1);

    load_chunk_async(W1s, W1, j0, tid);

    // ---------- prep: v, a-slice, straight points, boundaries ----------
    if (tid < DD) vsh[tid] = xT[g * DD + tid] - x0[g * DD + tid];
    __syncthreads();
    if (warp == 0) {
        float s = vsh[lane] * vsh[lane] + vsh[lane + 32] * vsh[lane + 32];
        #pragma unroll
        for (int o = 16; o; o >>= 1) s += __shfl_xor_sync(0xffffffffu, s, o);
        if (lane == 0) red[0] = 1.0f / sqrtf(s);
    }
    __syncthreads();
    {
        float inv = red[0];
        if (tid < DD) vsh[tid] *= inv;
    }
    __syncthreads();
    {
        const float4* w2r = (const float4*)(W2 + (size_t)(j0 + tid) * O);
        const float4* v4  = (const float4*)vsh;
        float acc = 0.f;
        #pragma unroll
        for (int k = 0; k < DD / 4; ++k) {
            float4 w = w2r[k], vv = v4[k];
            acc += w.x * vv.x + w.y * vv.y + w.z * vv.z + w.w * vv.w;
        }
        a_sh[tid] = acc;
    }
    #pragma unroll
    for (int idx = tid; idx < DD * PG; idx += NT) {
        int m = idx >> 3, p = idx & 7;
        int pc = (p < nsPerB) ? p : (nsPerB - 1);
        float t = (float)(pc + 1) * invn1;
        float a0 = x0[g * DD + m];
        xp[m * PG + p] = a0 + t * (xT[g * DD + m] - a0);
    }
    if (c == 0 && tid < DD) {
        out[g * DD + tid] = x0[g * DD + tid];
        out[((n_steps - 1) * B + g) * DD + tid] = xT[g * DD + tid];
    }
    asm volatile("cp.async.wait_group 0;");
    __syncthreads();

    // ---------- phase A column: h_j for 8 points ----------
    int j = j0 + tid;
    float h0, h1, h2, h3, h4, h5, h6, h7;
    {
        float bj = b1[j];
        h0 = h1 = h2 = h3 = h4 = h5 = h6 = h7 = bj;
    }
    const float4* xp4 = (const float4*)xp;
    #pragma unroll 4
    for (int d = 0; d < DD; ++d) {
        float wv = W1s[d * CCH + tid];
        float4 xa = xp4[d * 2], xb = xp4[d * 2 + 1];
        h0 += xa.x * wv; h1 += xa.y * wv; h2 += xa.z * wv; h3 += xa.w * wv;
        h4 += xb.x * wv; h5 += xb.y * wv; h6 += xb.z * wv; h7 += xb.w * wv;
    }
    {
        float hv[PG] = {h0, h1, h2, h3, h4, h5, h6, h7};
        float a = a_sh[tid];
        #pragma unroll
        for (int p = 0; p < PG; ++p) {
            float t = tanhf(hv[p]);
            float sf = 1.0f - t * t;
            as_t[tid * PG + p]  = a * sf;
            asp_t[tid * PG + p] = a * (-2.0f * t * sf);
        }
    }
    __syncthreads();

    // ---------- phase A row: partial w, two point-halves ----------
    #pragma unroll
    for (int ph = 0; ph < 2; ++ph) {
        float acc[8][4];
        #pragma unroll
        for (int r = 0; r < 8; ++r)
            #pragma unroll
            for (int p = 0; p < 4; ++p) acc[r][p] = 0.f;
        #pragma unroll
        for (int jj = 0; jj < 8; ++jj) {
            int j2 = jj * 32 + lane;
            float4 av = ((const float4*)as_t)[j2 * 2 + ph];
            #pragma unroll
            for (int r = 0; r < 8; ++r) {
                float wv = W1s[(warp * 8 + r) * CCH + j2];
                acc[r][0] += wv * av.x; acc[r][1] += wv * av.y;
                acc[r][2] += wv * av.z; acc[r][3] += wv * av.w;
            }
        }
        #pragma unroll
        for (int r = 0; r < 8; ++r)
            #pragma unroll
            for (int p = 0; p < 4; ++p) {
                float v = acc[r][p];
                #pragma unroll
                for (int o = 16; o; o >>= 1) v += __shfl_xor_sync(0xffffffffu, v, o);
                if (lane == 0)
                    g_wpart[((g * NCHK + c) * DD + warp * 8 + r) * PG + ph * 4 + p] = v;
            }
    }

    // ---------- gate A: all 8 chunk-blocks of this group done ----------
    __syncthreads();
    __threadfence();
    if (tid == 0) {
        atomicAdd(&g_cntA[g], 1u);
        while (((volatile unsigned*)g_cntA)[g] < NCHK) __nanosleep(20);
    }
    __syncthreads();

    // ---------- phase B: reduce w ; q ; m ; partial corr ----------
    #pragma unroll
    for (int idx = tid; idx < DD * PG; idx += NT) {
        float s = 0.f;
        #pragma unroll
        for (int cc = 0; cc < NCHK; ++cc)
            s += __ldcg(&g_wpart[(g * NCHK + cc) * DD * PG + idx]);
        wp[idx] = s;
    }
    __syncthreads();

    float q0 = 0.f, q1 = 0.f, q2 = 0.f, q3 = 0.f, q4 = 0.f, q5 = 0.f, q6 = 0.f, q7 = 0.f;
    const float4* wp4 = (const float4*)wp;
    #pragma unroll 4
    for (int d = 0; d < DD; ++d) {
        float wv = W1s[d * CCH + tid];
        float4 wa = wp4[d * 2], wb = wp4[d * 2 + 1];
        q0 += wa.x * wv; q1 += wa.y * wv; q2 += wa.z * wv; q3 += wa.w * wv;
        q4 += wb.x * wv; q5 += wb.y * wv; q6 += wb.z * wv; q7 += wb.w * wv;
    }
    {
        float qv[PG] = {q0, q1, q2, q3, q4, q5, q6, q7};
        #pragma unroll
        for (int p = 0; p < PG; ++p)
            as_t[tid * PG + p] = asp_t[tid * PG + p] * qv[p];
    }
    __syncthreads();

    #pragma unroll
    for (int ph = 0; ph < 2; ++ph) {
        float acc[8][4];
        #pragma unroll
        for (int r = 0; r < 8; ++r)
            #pragma unroll
            for (int p = 0; p < 4; ++p) acc[r][p] = 0.f;
        #pragma unroll
        for (int jj = 0; jj < 8; ++jj) {
            int j2 = jj * 32 + lane;
            float4 av = ((const float4*)as_t)[j2 * 2 + ph];
            #pragma unroll
            for (int r = 0; r < 8; ++r) {
                float wv = W1s[(warp * 8 + r) * CCH + j2];
                acc[r][0] += wv * av.x; acc[r][1] += wv * av.y;
                acc[r][2] += wv * av.z; acc[r][3] += wv * av.w;
            }
        }
        #pragma unroll
        for (int r = 0; r < 8; ++r)
            #pragma unroll
            for (int p = 0; p < 4; ++p) {
                float v = acc[r][p];
                #pragma unroll
                for (int o = 16; o; o >>= 1) v += __shfl_xor_sync(0xffffffffu, v, o);
                if (lane == 0)
                    g_cpart[((g * NCHK + c) * DD + warp * 8 + r) * PG + ph * 4 + p] = v;
            }
    }

    // ---------- gate B + last-block epilogue ----------
    __syncthreads();
    __threadfence();
    if (tid == 0) {
        unsigned old = atomicAdd(&g_cntB[g], 1u);
        slast = (old == NCHK - 1);
    }
    __syncthreads();
    if (!slast) return;

    #pragma unroll
    for (int idx = tid; idx < DD * PG; idx += NT) {
        float s = 0.f;
        #pragma unroll
        for (int cc = 0; cc < NCHK; ++cc)
            s += __ldcg(&g_cpart[(g * NCHK + cc) * DD * PG + idx]);
        int d = idx >> 3, p = idx & 7;
        csh[p * DD + d] = -s;
    }
    __syncthreads();
    {
        int p = warp;                    // 8 warps == PG
        float c0 = csh[p * DD + lane], c1 = csh[p * DD + 32 + lane];
        float s = c0 * c0 + c1 * c1;
        #pragma unroll
        for (int o = 16; o; o >>= 1) s += __shfl_xor_sync(0xffffffffu, s, o);
        if (lane == 0) red[p] = fminf(sqrtf(s), 0.1f) * 0.1f;
    }
    __syncthreads();
    #pragma unroll
    for (int idx = tid; idx < DD * PG; idx += NT) {
        int p = idx >> 6, m = idx & (DD - 1);
        if (p < nsPerB) {
            float t = (float)(p + 1) * invn1;
            float tfac = t * (1.0f - t);
            float a0 = x0[g * DD + m];
            float xv = a0 + t * (xT[g * DD + m] - a0);
            out[((p + 1) * B + g) * DD + m] = xv + csh[p * DD + m] * tfac * red[p];
        }
    }
    if (tid == 0) {                      // reset for next graph replay
        g_cntA[g] = 0;
        g_cntB[g] = 0;
        __threadfence();
    }
}

extern "C" void kernel_launch(void* const* d_in, const int* in_sizes, int n_in,
                              void* d_out, int out_size)
{
    const float* x0 = (const float*)d_in[0];
    const float* xT = (const float*)d_in[1];
    const float* W1 = (const float*)d_in[2];
    const float* b1 = (const float*)d_in[3];
    const float* W2 = (const float*)d_in[4];
    float* out = (float*)d_out;

    int H = in_sizes[3];               // 2048
    int Dd = in_sizes[2] / H;          // 64
    int B = in_sizes[0] / Dd;          // 32
    int O = in_sizes[5];               // 64
    int n_steps = out_size / (B * Dd); // 10
    int nInterior = (n_steps - 2) * B; // 256

    if (nInterior <= 0) return;

    size_t smem = (size_t)(DD * CCH + CCH + 2 * CCH * PG + 3 * DD * PG + DD + 16)
                  * sizeof(float);
    static int attr_set = 0;
    if (!attr_set) {
        cudaFuncSetAttribute(geo_one, cudaFuncAttributeMaxDynamicSharedMemorySize, (int)smem);
        attr_set = 1;
    }
    dim3 grid(B, NCHK);
    geo_one<<<grid, NT, smem>>>(x0, xT, W1, b1, W2, out, B, O, n_steps, nInterior);
}